// round 1
// baseline (speedup 1.0000x reference)
#include <cuda_runtime.h>
#include <math.h>

// Problem dims
#define B 8
#define S 4096
#define F 128
#define T 16
#define THRESH 0.1f
#define EPS 1e-8f

// Scratch: per-(b,f) accumulators and inverse-std (1024 entries)
__device__ double g_sum[B * F];
__device__ double g_sumsq[B * F];
__device__ __align__(16) float g_inv[B * F];

__global__ void k_zero() {
    int i = blockIdx.x * blockDim.x + threadIdx.x;
    if (i < B * F) { g_sum[i] = 0.0; g_sumsq[i] = 0.0; }
}

// Accumulate sum / sumsq of diff along S for each (b,f).
// grid (32 s-chunks, B), block (128 f, 8 s-threads). Coalesced loads.
__global__ void k_acc(const float* __restrict__ x) {
    int f = threadIdx.x;         // 0..127
    int ty = threadIdx.y;        // 0..7
    int chunk = blockIdx.x;      // 0..31 (128 s each)
    int b = blockIdx.y;

    const float* base = x + (size_t)b * S * F;
    int s0 = chunk * 128;

    float s1 = 0.f, s2 = 0.f;
    #pragma unroll 4
    for (int i = ty; i < 128; i += 8) {
        int s = s0 + i;
        float cur = base[(size_t)s * F + f];
        float prv = (s == 0) ? cur : base[(size_t)(s - 1) * F + f];
        float d = cur - prv;
        s1 += d;
        s2 += d * d;
    }

    __shared__ float sh[8][128];
    sh[ty][f] = s1;
    __syncthreads();
    if (ty == 0) {
        float t = 0.f;
        #pragma unroll
        for (int j = 0; j < 8; j++) t += sh[j][f];
        atomicAdd(&g_sum[b * F + f], (double)t);
    }
    __syncthreads();
    sh[ty][f] = s2;
    __syncthreads();
    if (ty == 0) {
        float t = 0.f;
        #pragma unroll
        for (int j = 0; j < 8; j++) t += sh[j][f];
        atomicAdd(&g_sumsq[b * F + f], (double)t);
    }
}

__global__ void k_inv() {
    int i = blockIdx.x * blockDim.x + threadIdx.x;
    if (i < B * F) {
        double m = g_sum[i] / (double)S;
        double var = g_sumsq[i] / (double)S - m * m;
        if (var < 0.0) var = 0.0;
        float sd = (float)sqrt(var);
        g_inv[i] = 1.0f / (sd + EPS);
    }
}

// Main expansion: one float4 per thread over B*S*F/4 elements.
// 16 coalesced float4 stores per thread (phase pattern t%3).
__global__ void k_main(const float4* __restrict__ x, float4* __restrict__ out) {
    int i = blockIdx.x * blockDim.x + threadIdx.x;  // 0 .. B*S*(F/4)-1
    int f4 = i & 31;            // F/4 = 32
    int s  = (i >> 5) & 4095;
    int b  = i >> 17;

    float4 cur = x[i];
    float4 prv = (s == 0) ? cur : x[i - 32];

    const float4 inv4 = *reinterpret_cast<const float4*>(&g_inv[b * F + f4 * 4]);

    float ndx = (cur.x - prv.x) * inv4.x;
    float ndy = (cur.y - prv.y) * inv4.y;
    float ndz = (cur.z - prv.z) * inv4.z;
    float ndw = (cur.w - prv.w) * inv4.w;

    float4 pos, neg;
    const float4 zero = make_float4(0.f, 0.f, 0.f, 0.f);
    pos.x = (ndx >=  THRESH) ? 1.f : 0.f;
    pos.y = (ndy >=  THRESH) ? 1.f : 0.f;
    pos.z = (ndz >=  THRESH) ? 1.f : 0.f;
    pos.w = (ndw >=  THRESH) ? 1.f : 0.f;
    neg.x = (-ndx >= THRESH) ? 1.f : 0.f;
    neg.y = (-ndy >= THRESH) ? 1.f : 0.f;
    neg.z = (-ndz >= THRESH) ? 1.f : 0.f;
    neg.w = (-ndw >= THRESH) ? 1.f : 0.f;

    // out index (b,t,s,f4) = ((b*T + t)*S + s)*32 + f4
    const size_t tstride = (size_t)S * 32;
    size_t obase = ((size_t)b * T * S + s) * 32 + f4;

    #pragma unroll
    for (int t = 0; t < T; t++) {
        int ph = t % 3;
        out[obase + (size_t)t * tstride] = (ph == 0) ? pos : (ph == 1) ? neg : zero;
    }
}

extern "C" void kernel_launch(void* const* d_in, const int* in_sizes, int n_in,
                              void* d_out, int out_size) {
    const float* x = (const float*)d_in[0];
    float* out = (float*)d_out;

    k_zero<<<1, 1024>>>();
    dim3 bt(128, 8);
    dim3 gr(32, B);
    k_acc<<<gr, bt>>>(x);
    k_inv<<<1, 1024>>>();

    int n4 = B * S * (F / 4);          // 1,048,576 float4 threads
    k_main<<<n4 / 256, 256>>>((const float4*)x, (float4*)out);
}